// round 14
// baseline (speedup 1.0000x reference)
#include <cuda_runtime.h>
#include <cuda_bf16.h>
#include <cstdint>

#define BB 4
#define LL 2048
#define DD 1024
#define NH 16
#define HDIM 64
#define QKVN (NH * HDIM * 3)   // 3072
#define NROWS (BB * LL)        // 8192

// ---- scratch (static device globals; no dynamic allocation) ----
__device__ __nv_bfloat16 g_qkvb[(size_t)NROWS * QKVN];        // 48 MB
__device__ __nv_bfloat16 g_nvb[(size_t)NROWS * (NH * HDIM)];  // 16 MB
__device__ float         g_hbuf[(size_t)NROWS * DD];          // 32 MB
__device__ __nv_bfloat16 g_xb[(size_t)NROWS * DD];            // 16 MB
__device__ __nv_bfloat16 g_wbT[(size_t)QKVN * DD];            //  6 MB (W_fc^T)
__device__ __nv_bfloat16 g_w2bT[(size_t)DD * (NH * HDIM)];    //  2 MB (W_fc2^T)
__device__ __nv_bfloat16 g_vt[(size_t)BB * NH * HDIM * LL];   // 16 MB (V^T [b][h][d][seq])

__device__ __forceinline__ float swish_f(float v) {
    return v * (1.0f / (1.0f + __expf(-v)));
}

__device__ __forceinline__ unsigned pack_bf16(float lo, float hi) {
    unsigned r;
    asm("cvt.rn.bf16x2.f32 %0, %1, %2;" : "=r"(r) : "f"(hi), "f"(lo));
    return r;
}

__device__ __forceinline__ void cp16(void* dst, const void* src) {
    unsigned s = (unsigned)__cvta_generic_to_shared(dst);
    asm volatile("cp.async.cg.shared.global [%0], [%1], 16;\n" :: "r"(s), "l"(src));
}
#define CP_COMMIT() asm volatile("cp.async.commit_group;\n")

// m16n8k16 bf16 mma, accumulate in place.
__device__ __forceinline__ void mma_bf16(float c[4], const unsigned a[4],
                                         const unsigned b[2]) {
    asm volatile(
        "mma.sync.aligned.m16n8k16.row.col.f32.bf16.bf16.f32 "
        "{%0,%1,%2,%3}, {%4,%5,%6,%7}, {%8,%9}, {%0,%1,%2,%3};\n"
        : "+f"(c[0]), "+f"(c[1]), "+f"(c[2]), "+f"(c[3])
        : "r"(a[0]), "r"(a[1]), "r"(a[2]), "r"(a[3]), "r"(b[0]), "r"(b[1]));
}

// ldmatrix x4: four 8x8 b16 matrices; lanes 0-7/8-15/16-23/24-31 supply the
// row addresses of matrices 0..3.
__device__ __forceinline__ void ldsm_x4(unsigned r[4], unsigned saddr) {
    asm volatile("ldmatrix.sync.aligned.m8n8.x4.shared.b16 {%0,%1,%2,%3}, [%4];"
                 : "=r"(r[0]), "=r"(r[1]), "=r"(r[2]), "=r"(r[3]) : "r"(saddr));
}

// ============================================================================
// f32 -> bf16 elementwise convert.
// ============================================================================
__global__ void __launch_bounds__(256)
cvt_kernel(const float* __restrict__ in, __nv_bfloat16* __restrict__ out, int n4)
{
    int i = blockIdx.x * blockDim.x + threadIdx.x;
    if (i < n4) {
        float4 v = ((const float4*)in)[i];
        uint2 o;
        o.x = pack_bf16(v.x, v.y);
        o.y = pack_bf16(v.z, v.w);
        ((uint2*)out)[i] = o;
    }
}

// ============================================================================
// Transpose + convert: w [K][N] f32 -> wt [N][K] bf16. 64x64 tiles, 256 thr.
// ============================================================================
__global__ void __launch_bounds__(256)
transcvt_kernel(const float* __restrict__ w, __nv_bfloat16* __restrict__ wt,
                int K, int N)
{
    __shared__ float ts[64][65];
    const int n0 = blockIdx.x * 64, k0 = blockIdx.y * 64;
    const int tid = threadIdx.x;

    #pragma unroll
    for (int it = 0; it < 4; it++) {
        int fid = it * 256 + tid;
        int r = fid >> 4, c4 = (fid & 15) << 2;
        float4 v = *(const float4*)(w + (size_t)(k0 + r) * N + n0 + c4);
        ts[r][c4] = v.x; ts[r][c4 + 1] = v.y; ts[r][c4 + 2] = v.z; ts[r][c4 + 3] = v.w;
    }
    __syncthreads();

    #pragma unroll
    for (int it = 0; it < 8; it++) {
        int fid = it * 256 + tid;
        int nl = fid >> 5, j = fid & 31;
        unsigned pk = pack_bf16(ts[2 * j][nl], ts[2 * j + 1][nl]);
        *(unsigned*)(wt + (size_t)(n0 + nl) * K + k0 + 2 * j) = pk;
    }
}

// ============================================================================
// V^T transpose: qkvb V slice [seq][d] bf16 -> vt [b][h][d][seq] bf16.
// ============================================================================
__global__ void __launch_bounds__(256)
vtrans_kernel(const __nv_bfloat16* __restrict__ qkvb, __nv_bfloat16* __restrict__ vt)
{
    __shared__ __nv_bfloat16 ts[64][72];
    const int st = blockIdx.x, h = blockIdx.y, b = blockIdx.z;
    const int tid = threadIdx.x;
    const __nv_bfloat16* src = qkvb + ((size_t)b * LL + st * 64) * QKVN
                               + h * (3 * HDIM) + 2 * HDIM;

    #pragma unroll
    for (int it = 0; it < 8; it++) {
        int fid = it * 256 + tid;
        int r = fid >> 5, j = fid & 31;
        *(unsigned*)&ts[r][2 * j] = *(const unsigned*)(src + (size_t)r * QKVN + 2 * j);
    }
    __syncthreads();

    const size_t obase = ((size_t)(b * NH + h) * HDIM) * LL + st * 64;
    #pragma unroll
    for (int it = 0; it < 8; it++) {
        int fid = it * 256 + tid;
        int d = fid >> 5, j = fid & 31;
        __nv_bfloat162 p;
        p.x = ts[2 * j][d];
        p.y = ts[2 * j + 1][d];
        *(__nv_bfloat162*)(vt + obase + (size_t)d * LL + 2 * j) = p;
    }
}

// ============================================================================
// BF16 tensor-core GEMM with ldmatrix fragment loads. Block 128x128, ktile 64,
// 256 threads (8 warps 2x4, warp tile 64x32), m16n8k16, fp32 accum.
// A [M][K] bf16 row-major, BT [N][K] bf16 row-major. Double-buffered cp.async.
// smem stride 72 bf16 (144 B) -> ldmatrix row addresses conflict-free.
// EPI=0: C(bf16) = bf16(swish(A*B + bias));  EPI=1: C(f32) = skip + swish(...)
// ============================================================================
#define GSTR 72                      // bf16 per smem row
#define GROWB 144                    // bytes per smem row
#define GBUF_B 18432                 // bytes per stage per operand (128*144)
#define G_SMEM_BYTES (4 * GBUF_B)    // 73728

template <int EPI>
__global__ void __launch_bounds__(256, 2)
gemm_bf(const __nv_bfloat16* __restrict__ A, const __nv_bfloat16* __restrict__ BT,
        const float* __restrict__ bias, const float* __restrict__ skip,
        void* __restrict__ Cout, int M, int N, int K)
{
    extern __shared__ __nv_bfloat16 smb[];
    __nv_bfloat16* As = smb;                     // [2][128][72]
    __nv_bfloat16* Bs = smb + 2 * (128 * GSTR);  // [2][128][72]
    const unsigned asb = (unsigned)__cvta_generic_to_shared(As);
    const unsigned bsb = (unsigned)__cvta_generic_to_shared(Bs);

    const int tid = threadIdx.x;
    const int bm = blockIdx.y, bn = blockIdx.x;
    const int wid = tid >> 5, lane = tid & 31;
    const int wm = wid >> 2, wn = wid & 3;  // warp 64x32 tile
    const int lg = lane >> 2, lc = lane & 3;

    // ldmatrix per-lane address offsets (bytes)
    const unsigned lrow = lane & 15;
    const unsigned lcolb = (lane & 16) ? 16u : 0u;
    const unsigned aoff = (wm * 64 + lrow) * GROWB + lcolb;
    const unsigned boff = (wn * 32 + lrow) * GROWB + lcolb;

    const __nv_bfloat16* Ag = A + (size_t)bm * 128 * K;
    const __nv_bfloat16* Bg = BT + (size_t)bn * 128 * K;
    const int T = K / 64;

    #pragma unroll
    for (int it = 0; it < 4; it++) {
        int fid = it * 256 + tid;
        int r = fid >> 3, c = fid & 7;
        cp16(&As[r * GSTR + c * 8], Ag + (size_t)r * K + c * 8);
        cp16(&Bs[r * GSTR + c * 8], Bg + (size_t)r * K + c * 8);
    }
    CP_COMMIT();

    float acc[4][4][4] = {};

    for (int t = 0; t < T; t++) {
        const int cur = t & 1;
        if (t + 1 < T) {
            const int nb = cur ^ 1;
            const int k0 = (t + 1) * 64;
            #pragma unroll
            for (int it = 0; it < 4; it++) {
                int fid = it * 256 + tid;
                int r = fid >> 3, c = fid & 7;
                cp16(&As[nb * (128 * GSTR) + r * GSTR + c * 8],
                     Ag + (size_t)r * K + k0 + c * 8);
                cp16(&Bs[nb * (128 * GSTR) + r * GSTR + c * 8],
                     Bg + (size_t)r * K + k0 + c * 8);
            }
            CP_COMMIT();
            asm volatile("cp.async.wait_group 1;\n");
        } else {
            asm volatile("cp.async.wait_group 0;\n");
        }
        __syncthreads();

        const unsigned abuf = asb + cur * GBUF_B + aoff;
        const unsigned bbuf = bsb + cur * GBUF_B + boff;

        #pragma unroll
        for (int step = 0; step < 4; step++) {
            unsigned a[4][4], b[4][2];
            #pragma unroll
            for (int mf = 0; mf < 4; mf++)
                ldsm_x4(a[mf], abuf + mf * (16 * GROWB) + step * 32);
            #pragma unroll
            for (int p = 0; p < 2; p++) {
                unsigned r[4];
                ldsm_x4(r, bbuf + p * (16 * GROWB) + step * 32);
                b[2 * p][0] = r[0]; b[2 * p + 1][0] = r[1];
                b[2 * p][1] = r[2]; b[2 * p + 1][1] = r[3];
            }
            #pragma unroll
            for (int mf = 0; mf < 4; mf++)
                #pragma unroll
                for (int nf = 0; nf < 4; nf++)
                    mma_bf16(acc[mf][nf], a[mf], b[nf]);
        }
        __syncthreads();
    }

    // epilogue
    #pragma unroll
    for (int mf = 0; mf < 4; mf++) {
        const size_t r0 = (size_t)bm * 128 + wm * 64 + mf * 16 + lg;
        #pragma unroll
        for (int nf = 0; nf < 4; nf++) {
            const int c = bn * 128 + wn * 32 + nf * 8 + lc * 2;
            const float b0 = bias[c], b1 = bias[c + 1];
            float v00 = swish_f(acc[mf][nf][0] + b0);
            float v01 = swish_f(acc[mf][nf][1] + b1);
            float v10 = swish_f(acc[mf][nf][2] + b0);
            float v11 = swish_f(acc[mf][nf][3] + b1);
            if (EPI == 1) {
                float* C = (float*)Cout;
                v00 += skip[r0 * (size_t)N + c];
                v01 += skip[r0 * (size_t)N + c + 1];
                v10 += skip[(r0 + 8) * (size_t)N + c];
                v11 += skip[(r0 + 8) * (size_t)N + c + 1];
                *(float2*)&C[r0 * (size_t)N + c] = make_float2(v00, v01);
                *(float2*)&C[(r0 + 8) * (size_t)N + c] = make_float2(v10, v11);
            } else {
                __nv_bfloat16* C = (__nv_bfloat16*)Cout;
                *(unsigned*)&C[r0 * (size_t)N + c] = pack_bf16(v00, v01);
                *(unsigned*)&C[(r0 + 8) * (size_t)N + c] = pack_bf16(v10, v11);
            }
        }
    }
}

// ============================================================================
// FlashAttention-2, all-bf16 operands, ldmatrix K/V fragment loads.
// Block = (qt 64 rows, h, b), 128 thr (4 warps), warp owns 16 Q rows x 64 keys.
// ============================================================================
#define ATK 72
#define ATV 72
#define AROWB 144                // bytes per smem row
#define AK_BUF_B (64 * AROWB)    // 9216 bytes per K stage
#define AV_BUF_B (64 * AROWB)    // 9216 bytes per V stage
#define A_SMEM_BYTES (2 * AK_BUF_B + 2 * AV_BUF_B)  // 36864

__global__ void __launch_bounds__(128, 4)
attn_fa(const __nv_bfloat16* __restrict__ qkvb, const __nv_bfloat16* __restrict__ vt,
        __nv_bfloat16* __restrict__ nvb)
{
    extern __shared__ char smraw[];
    __nv_bfloat16* Ks = (__nv_bfloat16*)smraw;
    __nv_bfloat16* Vs = (__nv_bfloat16*)(smraw + 2 * AK_BUF_B);
    const unsigned ks0 = (unsigned)__cvta_generic_to_shared(Ks);
    const unsigned vs0 = (unsigned)__cvta_generic_to_shared(Vs);

    const int qt = blockIdx.x, h = blockIdx.y, b = blockIdx.z;
    const int tid = threadIdx.x, wid = tid >> 5, lane = tid & 31;
    const int lg = lane >> 2, lc = lane & 3;
    const size_t rowbase = (size_t)b * LL;
    const int hoff = h * (3 * HDIM);
    const float scale = 0.022097086912079608f;  // 1/sqrt(2048)

    // ldmatrix per-lane offsets
    const unsigned lrow = lane & 15;
    const unsigned lcolb = (lane & 16) ? 16u : 0u;
    const unsigned lmoff = lrow * AROWB + lcolb;

    const __nv_bfloat16* kbase = qkvb + rowbase * QKVN + hoff + HDIM;
    const __nv_bfloat16* vtbase = vt + ((size_t)(b * NH + h) * HDIM) * LL;

    #pragma unroll
    for (int it = 0; it < 4; it++) {
        int fid = it * 128 + tid;
        int r = fid >> 3, c = fid & 7;
        cp16(&Ks[r * ATK + c * 8], kbase + (size_t)r * QKVN + c * 8);
        cp16(&Vs[r * ATV + c * 8], vtbase + (size_t)r * LL + c * 8);
    }
    CP_COMMIT();

    unsigned qa[4][4];
    {
        const __nv_bfloat16* qb = qkvb + (rowbase + qt * 64 + wid * 16) * QKVN + hoff;
        #pragma unroll
        for (int st = 0; st < 4; st++) {
            qa[st][0] = *(const unsigned*)(qb + (size_t)lg * QKVN + st * 16 + 2 * lc);
            qa[st][1] = *(const unsigned*)(qb + (size_t)(lg + 8) * QKVN + st * 16 + 2 * lc);
            qa[st][2] = *(const unsigned*)(qb + (size_t)lg * QKVN + st * 16 + 8 + 2 * lc);
            qa[st][3] = *(const unsigned*)(qb + (size_t)(lg + 8) * QKVN + st * 16 + 8 + 2 * lc);
        }
    }

    float o[8][4] = {};
    float m0 = -3.0e38f, m1 = -3.0e38f, l0 = 0.0f, l1 = 0.0f;

    for (int kt = 0; kt < LL / 64; kt++) {
        const int cur = kt & 1;
        if (kt + 1 < LL / 64) {
            const int nb = cur ^ 1;
            const __nv_bfloat16* kg = kbase + (size_t)(kt + 1) * 64 * QKVN;
            const __nv_bfloat16* vg = vtbase + (kt + 1) * 64;
            #pragma unroll
            for (int it = 0; it < 4; it++) {
                int fid = it * 128 + tid;
                int r = fid >> 3, c = fid & 7;
                cp16(&Ks[nb * (64 * ATK) + r * ATK + c * 8], kg + (size_t)r * QKVN + c * 8);
                cp16(&Vs[nb * (64 * ATV) + r * ATV + c * 8], vg + (size_t)r * LL + c * 8);
            }
            CP_COMMIT();
            asm volatile("cp.async.wait_group 1;\n");
        } else {
            asm volatile("cp.async.wait_group 0;\n");
        }
        __syncthreads();

        const unsigned kbuf = ks0 + cur * AK_BUF_B + lmoff;
        const unsigned vbuf = vs0 + cur * AV_BUF_B + lmoff;

        // S = Q K^T : 16x64 per warp; K fragments via ldmatrix (4 per step)
        float s[8][4] = {};
        #pragma unroll
        for (int st = 0; st < 4; st++) {
            unsigned kb[8][2];
            #pragma unroll
            for (int p = 0; p < 4; p++) {
                unsigned r[4];
                ldsm_x4(r, kbuf + p * (16 * AROWB) + st * 32);
                kb[2 * p][0] = r[0]; kb[2 * p + 1][0] = r[1];
                kb[2 * p][1] = r[2]; kb[2 * p + 1][1] = r[3];
            }
            #pragma unroll
            for (int nf = 0; nf < 8; nf++)
                mma_bf16(s[nf], qa[st], kb[nf]);
        }
        #pragma unroll
        for (int nf = 0; nf < 8; nf++) {
            s[nf][0] *= scale; s[nf][1] *= scale;
            s[nf][2] *= scale; s[nf][3] *= scale;
        }

        // in-register online softmax (rows lg -> m0/l0, lg+8 -> m1/l1)
        float mx0 = -3.0e38f, mx1 = -3.0e38f;
        #pragma unroll
        for (int nf = 0; nf < 8; nf++) {
            mx0 = fmaxf(mx0, fmaxf(s[nf][0], s[nf][1]));
            mx1 = fmaxf(mx1, fmaxf(s[nf][2], s[nf][3]));
        }
        mx0 = fmaxf(mx0, __shfl_xor_sync(0xffffffffu, mx0, 1));
        mx0 = fmaxf(mx0, __shfl_xor_sync(0xffffffffu, mx0, 2));
        mx1 = fmaxf(mx1, __shfl_xor_sync(0xffffffffu, mx1, 1));
        mx1 = fmaxf(mx1, __shfl_xor_sync(0xffffffffu, mx1, 2));
        const float mn0 = fmaxf(m0, mx0), mn1 = fmaxf(m1, mx1);
        const float al0 = __expf(m0 - mn0), al1 = __expf(m1 - mn1);
        m0 = mn0; m1 = mn1;

        float sum0 = 0.0f, sum1 = 0.0f;
        #pragma unroll
        for (int nf = 0; nf < 8; nf++) {
            s[nf][0] = __expf(s[nf][0] - mn0);
            s[nf][1] = __expf(s[nf][1] - mn0);
            s[nf][2] = __expf(s[nf][2] - mn1);
            s[nf][3] = __expf(s[nf][3] - mn1);
            sum0 += s[nf][0] + s[nf][1];
            sum1 += s[nf][2] + s[nf][3];
        }
        sum0 += __shfl_xor_sync(0xffffffffu, sum0, 1);
        sum0 += __shfl_xor_sync(0xffffffffu, sum0, 2);
        sum1 += __shfl_xor_sync(0xffffffffu, sum1, 1);
        sum1 += __shfl_xor_sync(0xffffffffu, sum1, 2);
        l0 = l0 * al0 + sum0;
        l1 = l1 * al1 + sum1;

        // rescale O
        #pragma unroll
        for (int nf = 0; nf < 8; nf++) {
            o[nf][0] *= al0; o[nf][1] *= al0;
            o[nf][2] *= al1; o[nf][3] *= al1;
        }

        // pack P -> bf16 A fragments
        unsigned pa[4][4];
        #pragma unroll
        for (int t = 0; t < 4; t++) {
            pa[t][0] = pack_bf16(s[2 * t][0], s[2 * t][1]);
            pa[t][1] = pack_bf16(s[2 * t][2], s[2 * t][3]);
            pa[t][2] = pack_bf16(s[2 * t + 1][0], s[2 * t + 1][1]);
            pa[t][3] = pack_bf16(s[2 * t + 1][2], s[2 * t + 1][3]);
        }

        // O += P V ; V fragments via ldmatrix (4 per t)
        #pragma unroll
        for (int t = 0; t < 4; t++) {
            unsigned vb[8][2];
            #pragma unroll
            for (int p = 0; p < 4; p++) {
                unsigned r[4];
                ldsm_x4(r, vbuf + p * (16 * AROWB) + t * 32);
                vb[2 * p][0] = r[0]; vb[2 * p + 1][0] = r[1];
                vb[2 * p][1] = r[2]; vb[2 * p + 1][1] = r[3];
            }
            #pragma unroll
            for (int nf = 0; nf < 8; nf++)
                mma_bf16(o[nf], pa[t], vb[nf]);
        }
        __syncthreads();
    }

    {
        const float li0 = 1.0f / l0, li1 = 1.0f / l1;
        const size_t row0 = rowbase + qt * 64 + wid * 16 + lg;
        #pragma unroll
        for (int nf = 0; nf < 8; nf++) {
            const int c = h * HDIM + nf * 8 + 2 * lc;
            *(unsigned*)&nvb[row0 * (size_t)(NH * HDIM) + c] =
                pack_bf16(o[nf][0] * li0, o[nf][1] * li0);
            *(unsigned*)&nvb[(row0 + 8) * (size_t)(NH * HDIM) + c] =
                pack_bf16(o[nf][2] * li1, o[nf][3] * li1);
        }
    }
}

// ============================================================================
// LayerNorm over D=1024. One block (256 threads) per row.
// ============================================================================
__global__ void __launch_bounds__(256)
ln_kernel(const float* __restrict__ hb, float* __restrict__ out)
{
    const int row = blockIdx.x;
    const float4* p4 = (const float4*)(hb + (size_t)row * DD);
    float4 v = p4[threadIdx.x];
    float s  = v.x + v.y + v.z + v.w;
    float s2 = v.x * v.x + v.y * v.y + v.z * v.z + v.w * v.w;

    __shared__ float rs[8], rs2[8];
    const int wid = threadIdx.x >> 5, lane = threadIdx.x & 31;
    #pragma unroll
    for (int off = 16; off > 0; off >>= 1) {
        s  += __shfl_xor_sync(0xffffffffu, s, off);
        s2 += __shfl_xor_sync(0xffffffffu, s2, off);
    }
    if (lane == 0) { rs[wid] = s; rs2[wid] = s2; }
    __syncthreads();
    if (threadIdx.x == 0) {
        float a = 0.f, b2 = 0.f;
        #pragma unroll
        for (int i = 0; i < 8; i++) { a += rs[i]; b2 += rs2[i]; }
        rs[0] = a; rs2[0] = b2;
    }
    __syncthreads();
    const float mu = rs[0] * (1.0f / DD);
    const float var = rs2[0] * (1.0f / DD) - mu * mu;
    const float rstd = rsqrtf(var + 1e-5f);
    float4 ov = make_float4((v.x - mu) * rstd, (v.y - mu) * rstd,
                            (v.z - mu) * rstd, (v.w - mu) * rstd);
    ((float4*)(out + (size_t)row * DD))[threadIdx.x] = ov;
}

// ============================================================================
extern "C" void kernel_launch(void* const* d_in, const int* in_sizes, int n_in,
                              void* d_out, int out_size)
{
    const float* x     = (const float*)d_in[0];
    const float* W_fc  = (const float*)d_in[1];
    const float* b_fc  = (const float*)d_in[2];
    const float* W_fc2 = (const float*)d_in[3];
    const float* b_fc2 = (const float*)d_in[4];
    float* out = (float*)d_out;

    void* p;
    cudaGetSymbolAddress(&p, g_qkvb);  __nv_bfloat16* qkvb = (__nv_bfloat16*)p;
    cudaGetSymbolAddress(&p, g_nvb);   __nv_bfloat16* nvb  = (__nv_bfloat16*)p;
    cudaGetSymbolAddress(&p, g_hbuf);  float* hb = (float*)p;
    cudaGetSymbolAddress(&p, g_xb);    __nv_bfloat16* xb   = (__nv_bfloat16*)p;
    cudaGetSymbolAddress(&p, g_wbT);   __nv_bfloat16* wbT  = (__nv_bfloat16*)p;
    cudaGetSymbolAddress(&p, g_w2bT);  __nv_bfloat16* w2bT = (__nv_bfloat16*)p;
    cudaGetSymbolAddress(&p, g_vt);    __nv_bfloat16* vt   = (__nv_bfloat16*)p;

    // Convert x -> bf16; transpose+convert weights -> [N][K] bf16.
    cvt_kernel<<<(NROWS * DD / 4) / 256, 256>>>(x, xb, NROWS * DD / 4);
    {
        dim3 gw(QKVN / 64, DD / 64);
        transcvt_kernel<<<gw, 256>>>(W_fc, wbT, DD, QKVN);
        dim3 gw2(DD / 64, (NH * HDIM) / 64);
        transcvt_kernel<<<gw2, 256>>>(W_fc2, w2bT, NH * HDIM, DD);
    }

    cudaFuncSetAttribute(gemm_bf<0>, cudaFuncAttributeMaxDynamicSharedMemorySize, G_SMEM_BYTES);
    cudaFuncSetAttribute(gemm_bf<1>, cudaFuncAttributeMaxDynamicSharedMemorySize, G_SMEM_BYTES);

    // GEMM1: qkvb = bf16(swish(x @ W_fc + b_fc))
    dim3 g1(QKVN / 128, NROWS / 128);
    gemm_bf<0><<<g1, 256, G_SMEM_BYTES>>>(xb, wbT, b_fc, nullptr, qkvb, NROWS, QKVN, DD);

    // V^T for the PV mma
    dim3 gv(LL / 64, NH, BB);
    vtrans_kernel<<<gv, 256>>>(qkvb, vt);

    // FlashAttention-2 (bf16, ldmatrix)
    cudaFuncSetAttribute(attn_fa, cudaFuncAttributeMaxDynamicSharedMemorySize, A_SMEM_BYTES);
    dim3 ga(LL / 64, NH, BB);
    attn_fa<<<ga, 128, A_SMEM_BYTES>>>(qkvb, vt, nvb);

    // GEMM2: hb = x + swish(nv @ W_fc2 + b_fc2)
    dim3 g2(DD / 128, NROWS / 128);
    gemm_bf<1><<<g2, 256, G_SMEM_BYTES>>>(nvb, w2bT, b_fc2, x, hb, NROWS, DD, DD);

    // LayerNorm -> out
    ln_kernel<<<NROWS, 256>>>(hb, out);
}

// round 15
// speedup vs baseline: 1.0005x; 1.0005x over previous
#include <cuda_runtime.h>
#include <cuda_bf16.h>
#include <cstdint>

#define BB 4
#define LL 2048
#define DD 1024
#define NH 16
#define HDIM 64
#define QKVN (NH * HDIM * 3)   // 3072
#define NROWS (BB * LL)        // 8192

// ---- scratch (static device globals; no dynamic allocation) ----
__device__ __nv_bfloat16 g_qkvb[(size_t)NROWS * QKVN];        // 48 MB
__device__ __nv_bfloat16 g_nvb[(size_t)NROWS * (NH * HDIM)];  // 16 MB
__device__ float         g_hbuf[(size_t)NROWS * DD];          // 32 MB
__device__ __nv_bfloat16 g_xb[(size_t)NROWS * DD];            // 16 MB
__device__ __nv_bfloat16 g_wbT[(size_t)QKVN * DD];            //  6 MB (W_fc^T)
__device__ __nv_bfloat16 g_w2bT[(size_t)DD * (NH * HDIM)];    //  2 MB (W_fc2^T)
__device__ __nv_bfloat16 g_vt[(size_t)BB * NH * HDIM * LL];   // 16 MB (V^T [b][h][d][seq])

__device__ __forceinline__ float swish_f(float v) {
    return v * (1.0f / (1.0f + __expf(-v)));
}

__device__ __forceinline__ unsigned pack_bf16(float lo, float hi) {
    unsigned r;
    asm("cvt.rn.bf16x2.f32 %0, %1, %2;" : "=r"(r) : "f"(hi), "f"(lo));
    return r;
}

__device__ __forceinline__ void cp16(void* dst, const void* src) {
    unsigned s = (unsigned)__cvta_generic_to_shared(dst);
    asm volatile("cp.async.cg.shared.global [%0], [%1], 16;\n" :: "r"(s), "l"(src));
}
#define CP_COMMIT() asm volatile("cp.async.commit_group;\n")

// m16n8k16 bf16 mma, accumulate in place.
__device__ __forceinline__ void mma_bf16(float c[4], const unsigned a[4],
                                         const unsigned b[2]) {
    asm volatile(
        "mma.sync.aligned.m16n8k16.row.col.f32.bf16.bf16.f32 "
        "{%0,%1,%2,%3}, {%4,%5,%6,%7}, {%8,%9}, {%0,%1,%2,%3};\n"
        : "+f"(c[0]), "+f"(c[1]), "+f"(c[2]), "+f"(c[3])
        : "r"(a[0]), "r"(a[1]), "r"(a[2]), "r"(a[3]), "r"(b[0]), "r"(b[1]));
}

// ldmatrix x4: four 8x8 b16 matrices; lanes 0-7/8-15/16-23/24-31 supply the
// row addresses of matrices 0..3.
__device__ __forceinline__ void ldsm_x4(unsigned r[4], unsigned saddr) {
    asm volatile("ldmatrix.sync.aligned.m8n8.x4.shared.b16 {%0,%1,%2,%3}, [%4];"
                 : "=r"(r[0]), "=r"(r[1]), "=r"(r[2]), "=r"(r[3]) : "r"(saddr));
}

// ============================================================================
// f32 -> bf16 elementwise convert.
// ============================================================================
__global__ void __launch_bounds__(256)
cvt_kernel(const float* __restrict__ in, __nv_bfloat16* __restrict__ out, int n4)
{
    int i = blockIdx.x * blockDim.x + threadIdx.x;
    if (i < n4) {
        float4 v = ((const float4*)in)[i];
        uint2 o;
        o.x = pack_bf16(v.x, v.y);
        o.y = pack_bf16(v.z, v.w);
        ((uint2*)out)[i] = o;
    }
}

// ============================================================================
// Transpose + convert: w [K][N] f32 -> wt [N][K] bf16. 64x64 tiles, 256 thr.
// ============================================================================
__global__ void __launch_bounds__(256)
transcvt_kernel(const float* __restrict__ w, __nv_bfloat16* __restrict__ wt,
                int K, int N)
{
    __shared__ float ts[64][65];
    const int n0 = blockIdx.x * 64, k0 = blockIdx.y * 64;
    const int tid = threadIdx.x;

    #pragma unroll
    for (int it = 0; it < 4; it++) {
        int fid = it * 256 + tid;
        int r = fid >> 4, c4 = (fid & 15) << 2;
        float4 v = *(const float4*)(w + (size_t)(k0 + r) * N + n0 + c4);
        ts[r][c4] = v.x; ts[r][c4 + 1] = v.y; ts[r][c4 + 2] = v.z; ts[r][c4 + 3] = v.w;
    }
    __syncthreads();

    #pragma unroll
    for (int it = 0; it < 8; it++) {
        int fid = it * 256 + tid;
        int nl = fid >> 5, j = fid & 31;
        unsigned pk = pack_bf16(ts[2 * j][nl], ts[2 * j + 1][nl]);
        *(unsigned*)(wt + (size_t)(n0 + nl) * K + k0 + 2 * j) = pk;
    }
}

// ============================================================================
// V^T transpose: qkvb V slice [seq][d] bf16 -> vt [b][h][d][seq] bf16.
// ============================================================================
__global__ void __launch_bounds__(256)
vtrans_kernel(const __nv_bfloat16* __restrict__ qkvb, __nv_bfloat16* __restrict__ vt)
{
    __shared__ __nv_bfloat16 ts[64][72];
    const int st = blockIdx.x, h = blockIdx.y, b = blockIdx.z;
    const int tid = threadIdx.x;
    const __nv_bfloat16* src = qkvb + ((size_t)b * LL + st * 64) * QKVN
                               + h * (3 * HDIM) + 2 * HDIM;

    #pragma unroll
    for (int it = 0; it < 8; it++) {
        int fid = it * 256 + tid;
        int r = fid >> 5, j = fid & 31;
        *(unsigned*)&ts[r][2 * j] = *(const unsigned*)(src + (size_t)r * QKVN + 2 * j);
    }
    __syncthreads();

    const size_t obase = ((size_t)(b * NH + h) * HDIM) * LL + st * 64;
    #pragma unroll
    for (int it = 0; it < 8; it++) {
        int fid = it * 256 + tid;
        int d = fid >> 5, j = fid & 31;
        __nv_bfloat162 p;
        p.x = ts[2 * j][d];
        p.y = ts[2 * j + 1][d];
        *(__nv_bfloat162*)(vt + obase + (size_t)d * LL + 2 * j) = p;
    }
}

// ============================================================================
// BF16 tensor-core GEMM with ldmatrix fragment loads. Block 128x128, ktile 64,
// 256 threads (8 warps 2x4, warp tile 64x32), m16n8k16, fp32 accum.
// A [M][K] bf16 row-major, BT [N][K] bf16 row-major. Double-buffered cp.async.
// smem stride 72 bf16 (144 B) -> ldmatrix row addresses conflict-free.
// EPI=0: C(bf16) = bf16(swish(A*B + bias));  EPI=1: C(f32) = skip + swish(...)
// ============================================================================
#define GSTR 72                      // bf16 per smem row
#define GROWB 144                    // bytes per smem row
#define GBUF_B 18432                 // bytes per stage per operand (128*144)
#define G_SMEM_BYTES (4 * GBUF_B)    // 73728

template <int EPI>
__global__ void __launch_bounds__(256, 2)
gemm_bf(const __nv_bfloat16* __restrict__ A, const __nv_bfloat16* __restrict__ BT,
        const float* __restrict__ bias, const float* __restrict__ skip,
        void* __restrict__ Cout, int M, int N, int K)
{
    extern __shared__ __nv_bfloat16 smb[];
    __nv_bfloat16* As = smb;                     // [2][128][72]
    __nv_bfloat16* Bs = smb + 2 * (128 * GSTR);  // [2][128][72]
    const unsigned asb = (unsigned)__cvta_generic_to_shared(As);
    const unsigned bsb = (unsigned)__cvta_generic_to_shared(Bs);

    const int tid = threadIdx.x;
    const int bm = blockIdx.y, bn = blockIdx.x;
    const int wid = tid >> 5, lane = tid & 31;
    const int wm = wid >> 2, wn = wid & 3;  // warp 64x32 tile
    const int lg = lane >> 2, lc = lane & 3;

    // ldmatrix per-lane address offsets (bytes)
    const unsigned lrow = lane & 15;
    const unsigned lcolb = (lane & 16) ? 16u : 0u;
    const unsigned aoff = (wm * 64 + lrow) * GROWB + lcolb;
    const unsigned boff = (wn * 32 + lrow) * GROWB + lcolb;

    const __nv_bfloat16* Ag = A + (size_t)bm * 128 * K;
    const __nv_bfloat16* Bg = BT + (size_t)bn * 128 * K;
    const int T = K / 64;

    #pragma unroll
    for (int it = 0; it < 4; it++) {
        int fid = it * 256 + tid;
        int r = fid >> 3, c = fid & 7;
        cp16(&As[r * GSTR + c * 8], Ag + (size_t)r * K + c * 8);
        cp16(&Bs[r * GSTR + c * 8], Bg + (size_t)r * K + c * 8);
    }
    CP_COMMIT();

    float acc[4][4][4] = {};

    for (int t = 0; t < T; t++) {
        const int cur = t & 1;
        if (t + 1 < T) {
            const int nb = cur ^ 1;
            const int k0 = (t + 1) * 64;
            #pragma unroll
            for (int it = 0; it < 4; it++) {
                int fid = it * 256 + tid;
                int r = fid >> 3, c = fid & 7;
                cp16(&As[nb * (128 * GSTR) + r * GSTR + c * 8],
                     Ag + (size_t)r * K + k0 + c * 8);
                cp16(&Bs[nb * (128 * GSTR) + r * GSTR + c * 8],
                     Bg + (size_t)r * K + k0 + c * 8);
            }
            CP_COMMIT();
            asm volatile("cp.async.wait_group 1;\n");
        } else {
            asm volatile("cp.async.wait_group 0;\n");
        }
        __syncthreads();

        const unsigned abuf = asb + cur * GBUF_B + aoff;
        const unsigned bbuf = bsb + cur * GBUF_B + boff;

        #pragma unroll
        for (int step = 0; step < 4; step++) {
            unsigned a[4][4], b[4][2];
            #pragma unroll
            for (int mf = 0; mf < 4; mf++)
                ldsm_x4(a[mf], abuf + mf * (16 * GROWB) + step * 32);
            #pragma unroll
            for (int p = 0; p < 2; p++) {
                unsigned r[4];
                ldsm_x4(r, bbuf + p * (16 * GROWB) + step * 32);
                b[2 * p][0] = r[0]; b[2 * p + 1][0] = r[1];
                b[2 * p][1] = r[2]; b[2 * p + 1][1] = r[3];
            }
            #pragma unroll
            for (int mf = 0; mf < 4; mf++)
                #pragma unroll
                for (int nf = 0; nf < 4; nf++)
                    mma_bf16(acc[mf][nf], a[mf], b[nf]);
        }
        __syncthreads();
    }

    // epilogue
    #pragma unroll
    for (int mf = 0; mf < 4; mf++) {
        const size_t r0 = (size_t)bm * 128 + wm * 64 + mf * 16 + lg;
        #pragma unroll
        for (int nf = 0; nf < 4; nf++) {
            const int c = bn * 128 + wn * 32 + nf * 8 + lc * 2;
            const float b0 = bias[c], b1 = bias[c + 1];
            float v00 = swish_f(acc[mf][nf][0] + b0);
            float v01 = swish_f(acc[mf][nf][1] + b1);
            float v10 = swish_f(acc[mf][nf][2] + b0);
            float v11 = swish_f(acc[mf][nf][3] + b1);
            if (EPI == 1) {
                float* C = (float*)Cout;
                v00 += skip[r0 * (size_t)N + c];
                v01 += skip[r0 * (size_t)N + c + 1];
                v10 += skip[(r0 + 8) * (size_t)N + c];
                v11 += skip[(r0 + 8) * (size_t)N + c + 1];
                *(float2*)&C[r0 * (size_t)N + c] = make_float2(v00, v01);
                *(float2*)&C[(r0 + 8) * (size_t)N + c] = make_float2(v10, v11);
            } else {
                __nv_bfloat16* C = (__nv_bfloat16*)Cout;
                *(unsigned*)&C[r0 * (size_t)N + c] = pack_bf16(v00, v01);
                *(unsigned*)&C[(r0 + 8) * (size_t)N + c] = pack_bf16(v10, v11);
            }
        }
    }
}

// ============================================================================
// FlashAttention-2, all-bf16 operands, ldmatrix K/V fragment loads.
// Block = (qt 64 rows, h, b), 128 thr (4 warps), warp owns 16 Q rows x 64 keys.
// ============================================================================
#define ATK 72
#define ATV 72
#define AROWB 144                // bytes per smem row
#define AK_BUF_B (64 * AROWB)    // 9216 bytes per K stage
#define AV_BUF_B (64 * AROWB)    // 9216 bytes per V stage
#define A_SMEM_BYTES (2 * AK_BUF_B + 2 * AV_BUF_B)  // 36864

__global__ void __launch_bounds__(128, 4)
attn_fa(const __nv_bfloat16* __restrict__ qkvb, const __nv_bfloat16* __restrict__ vt,
        __nv_bfloat16* __restrict__ nvb)
{
    extern __shared__ char smraw[];
    __nv_bfloat16* Ks = (__nv_bfloat16*)smraw;
    __nv_bfloat16* Vs = (__nv_bfloat16*)(smraw + 2 * AK_BUF_B);
    const unsigned ks0 = (unsigned)__cvta_generic_to_shared(Ks);
    const unsigned vs0 = (unsigned)__cvta_generic_to_shared(Vs);

    const int qt = blockIdx.x, h = blockIdx.y, b = blockIdx.z;
    const int tid = threadIdx.x, wid = tid >> 5, lane = tid & 31;
    const int lg = lane >> 2, lc = lane & 3;
    const size_t rowbase = (size_t)b * LL;
    const int hoff = h * (3 * HDIM);
    const float scale = 0.022097086912079608f;  // 1/sqrt(2048)

    // ldmatrix per-lane offsets
    const unsigned lrow = lane & 15;
    const unsigned lcolb = (lane & 16) ? 16u : 0u;
    const unsigned lmoff = lrow * AROWB + lcolb;

    const __nv_bfloat16* kbase = qkvb + rowbase * QKVN + hoff + HDIM;
    const __nv_bfloat16* vtbase = vt + ((size_t)(b * NH + h) * HDIM) * LL;

    #pragma unroll
    for (int it = 0; it < 4; it++) {
        int fid = it * 128 + tid;
        int r = fid >> 3, c = fid & 7;
        cp16(&Ks[r * ATK + c * 8], kbase + (size_t)r * QKVN + c * 8);
        cp16(&Vs[r * ATV + c * 8], vtbase + (size_t)r * LL + c * 8);
    }
    CP_COMMIT();

    unsigned qa[4][4];
    {
        const __nv_bfloat16* qb = qkvb + (rowbase + qt * 64 + wid * 16) * QKVN + hoff;
        #pragma unroll
        for (int st = 0; st < 4; st++) {
            qa[st][0] = *(const unsigned*)(qb + (size_t)lg * QKVN + st * 16 + 2 * lc);
            qa[st][1] = *(const unsigned*)(qb + (size_t)(lg + 8) * QKVN + st * 16 + 2 * lc);
            qa[st][2] = *(const unsigned*)(qb + (size_t)lg * QKVN + st * 16 + 8 + 2 * lc);
            qa[st][3] = *(const unsigned*)(qb + (size_t)(lg + 8) * QKVN + st * 16 + 8 + 2 * lc);
        }
    }

    float o[8][4] = {};
    float m0 = -3.0e38f, m1 = -3.0e38f, l0 = 0.0f, l1 = 0.0f;

    for (int kt = 0; kt < LL / 64; kt++) {
        const int cur = kt & 1;
        if (kt + 1 < LL / 64) {
            const int nb = cur ^ 1;
            const __nv_bfloat16* kg = kbase + (size_t)(kt + 1) * 64 * QKVN;
            const __nv_bfloat16* vg = vtbase + (kt + 1) * 64;
            #pragma unroll
            for (int it = 0; it < 4; it++) {
                int fid = it * 128 + tid;
                int r = fid >> 3, c = fid & 7;
                cp16(&Ks[nb * (64 * ATK) + r * ATK + c * 8], kg + (size_t)r * QKVN + c * 8);
                cp16(&Vs[nb * (64 * ATV) + r * ATV + c * 8], vg + (size_t)r * LL + c * 8);
            }
            CP_COMMIT();
            asm volatile("cp.async.wait_group 1;\n");
        } else {
            asm volatile("cp.async.wait_group 0;\n");
        }
        __syncthreads();

        const unsigned kbuf = ks0 + cur * AK_BUF_B + lmoff;
        const unsigned vbuf = vs0 + cur * AV_BUF_B + lmoff;

        // S = Q K^T : 16x64 per warp; K fragments via ldmatrix (4 per step)
        float s[8][4] = {};
        #pragma unroll
        for (int st = 0; st < 4; st++) {
            unsigned kb[8][2];
            #pragma unroll
            for (int p = 0; p < 4; p++) {
                unsigned r[4];
                ldsm_x4(r, kbuf + p * (16 * AROWB) + st * 32);
                kb[2 * p][0] = r[0]; kb[2 * p + 1][0] = r[1];
                kb[2 * p][1] = r[2]; kb[2 * p + 1][1] = r[3];
            }
            #pragma unroll
            for (int nf = 0; nf < 8; nf++)
                mma_bf16(s[nf], qa[st], kb[nf]);
        }
        #pragma unroll
        for (int nf = 0; nf < 8; nf++) {
            s[nf][0] *= scale; s[nf][1] *= scale;
            s[nf][2] *= scale; s[nf][3] *= scale;
        }

        // in-register online softmax (rows lg -> m0/l0, lg+8 -> m1/l1)
        float mx0 = -3.0e38f, mx1 = -3.0e38f;
        #pragma unroll
        for (int nf = 0; nf < 8; nf++) {
            mx0 = fmaxf(mx0, fmaxf(s[nf][0], s[nf][1]));
            mx1 = fmaxf(mx1, fmaxf(s[nf][2], s[nf][3]));
        }
        mx0 = fmaxf(mx0, __shfl_xor_sync(0xffffffffu, mx0, 1));
        mx0 = fmaxf(mx0, __shfl_xor_sync(0xffffffffu, mx0, 2));
        mx1 = fmaxf(mx1, __shfl_xor_sync(0xffffffffu, mx1, 1));
        mx1 = fmaxf(mx1, __shfl_xor_sync(0xffffffffu, mx1, 2));
        const float mn0 = fmaxf(m0, mx0), mn1 = fmaxf(m1, mx1);
        const float al0 = __expf(m0 - mn0), al1 = __expf(m1 - mn1);
        m0 = mn0; m1 = mn1;

        float sum0 = 0.0f, sum1 = 0.0f;
        #pragma unroll
        for (int nf = 0; nf < 8; nf++) {
            s[nf][0] = __expf(s[nf][0] - mn0);
            s[nf][1] = __expf(s[nf][1] - mn0);
            s[nf][2] = __expf(s[nf][2] - mn1);
            s[nf][3] = __expf(s[nf][3] - mn1);
            sum0 += s[nf][0] + s[nf][1];
            sum1 += s[nf][2] + s[nf][3];
        }
        sum0 += __shfl_xor_sync(0xffffffffu, sum0, 1);
        sum0 += __shfl_xor_sync(0xffffffffu, sum0, 2);
        sum1 += __shfl_xor_sync(0xffffffffu, sum1, 1);
        sum1 += __shfl_xor_sync(0xffffffffu, sum1, 2);
        l0 = l0 * al0 + sum0;
        l1 = l1 * al1 + sum1;

        // rescale O
        #pragma unroll
        for (int nf = 0; nf < 8; nf++) {
            o[nf][0] *= al0; o[nf][1] *= al0;
            o[nf][2] *= al1; o[nf][3] *= al1;
        }

        // pack P -> bf16 A fragments
        unsigned pa[4][4];
        #pragma unroll
        for (int t = 0; t < 4; t++) {
            pa[t][0] = pack_bf16(s[2 * t][0], s[2 * t][1]);
            pa[t][1] = pack_bf16(s[2 * t][2], s[2 * t][3]);
            pa[t][2] = pack_bf16(s[2 * t + 1][0], s[2 * t + 1][1]);
            pa[t][3] = pack_bf16(s[2 * t + 1][2], s[2 * t + 1][3]);
        }

        // O += P V ; V fragments via ldmatrix (4 per t)
        #pragma unroll
        for (int t = 0; t < 4; t++) {
            unsigned vb[8][2];
            #pragma unroll
            for (int p = 0; p < 4; p++) {
                unsigned r[4];
                ldsm_x4(r, vbuf + p * (16 * AROWB) + t * 32);
                vb[2 * p][0] = r[0]; vb[2 * p + 1][0] = r[1];
                vb[2 * p][1] = r[2]; vb[2 * p + 1][1] = r[3];
            }
            #pragma unroll
            for (int nf = 0; nf < 8; nf++)
                mma_bf16(o[nf], pa[t], vb[nf]);
        }
        __syncthreads();
    }

    {
        const float li0 = 1.0f / l0, li1 = 1.0f / l1;
        const size_t row0 = rowbase + qt * 64 + wid * 16 + lg;
        #pragma unroll
        for (int nf = 0; nf < 8; nf++) {
            const int c = h * HDIM + nf * 8 + 2 * lc;
            *(unsigned*)&nvb[row0 * (size_t)(NH * HDIM) + c] =
                pack_bf16(o[nf][0] * li0, o[nf][1] * li0);
            *(unsigned*)&nvb[(row0 + 8) * (size_t)(NH * HDIM) + c] =
                pack_bf16(o[nf][2] * li1, o[nf][3] * li1);
        }
    }
}

// ============================================================================
// LayerNorm over D=1024. One block (256 threads) per row.
// ============================================================================
__global__ void __launch_bounds__(256)
ln_kernel(const float* __restrict__ hb, float* __restrict__ out)
{
    const int row = blockIdx.x;
    const float4* p4 = (const float4*)(hb + (size_t)row * DD);
    float4 v = p4[threadIdx.x];
    float s  = v.x + v.y + v.z + v.w;
    float s2 = v.x * v.x + v.y * v.y + v.z * v.z + v.w * v.w;

    __shared__ float rs[8], rs2[8];
    const int wid = threadIdx.x >> 5, lane = threadIdx.x & 31;
    #pragma unroll
    for (int off = 16; off > 0; off >>= 1) {
        s  += __shfl_xor_sync(0xffffffffu, s, off);
        s2 += __shfl_xor_sync(0xffffffffu, s2, off);
    }
    if (lane == 0) { rs[wid] = s; rs2[wid] = s2; }
    __syncthreads();
    if (threadIdx.x == 0) {
        float a = 0.f, b2 = 0.f;
        #pragma unroll
        for (int i = 0; i < 8; i++) { a += rs[i]; b2 += rs2[i]; }
        rs[0] = a; rs2[0] = b2;
    }
    __syncthreads();
    const float mu = rs[0] * (1.0f / DD);
    const float var = rs2[0] * (1.0f / DD) - mu * mu;
    const float rstd = rsqrtf(var + 1e-5f);
    float4 ov = make_float4((v.x - mu) * rstd, (v.y - mu) * rstd,
                            (v.z - mu) * rstd, (v.w - mu) * rstd);
    ((float4*)(out + (size_t)row * DD))[threadIdx.x] = ov;
}

// ============================================================================
extern "C" void kernel_launch(void* const* d_in, const int* in_sizes, int n_in,
                              void* d_out, int out_size)
{
    const float* x     = (const float*)d_in[0];
    const float* W_fc  = (const float*)d_in[1];
    const float* b_fc  = (const float*)d_in[2];
    const float* W_fc2 = (const float*)d_in[3];
    const float* b_fc2 = (const float*)d_in[4];
    float* out = (float*)d_out;

    void* p;
    cudaGetSymbolAddress(&p, g_qkvb);  __nv_bfloat16* qkvb = (__nv_bfloat16*)p;
    cudaGetSymbolAddress(&p, g_nvb);   __nv_bfloat16* nvb  = (__nv_bfloat16*)p;
    cudaGetSymbolAddress(&p, g_hbuf);  float* hb = (float*)p;
    cudaGetSymbolAddress(&p, g_xb);    __nv_bfloat16* xb   = (__nv_bfloat16*)p;
    cudaGetSymbolAddress(&p, g_wbT);   __nv_bfloat16* wbT  = (__nv_bfloat16*)p;
    cudaGetSymbolAddress(&p, g_w2bT);  __nv_bfloat16* w2bT = (__nv_bfloat16*)p;
    cudaGetSymbolAddress(&p, g_vt);    __nv_bfloat16* vt   = (__nv_bfloat16*)p;

    // Convert x -> bf16; transpose+convert weights -> [N][K] bf16.
    cvt_kernel<<<(NROWS * DD / 4) / 256, 256>>>(x, xb, NROWS * DD / 4);
    {
        dim3 gw(QKVN / 64, DD / 64);
        transcvt_kernel<<<gw, 256>>>(W_fc, wbT, DD, QKVN);
        dim3 gw2(DD / 64, (NH * HDIM) / 64);
        transcvt_kernel<<<gw2, 256>>>(W_fc2, w2bT, NH * HDIM, DD);
    }

    cudaFuncSetAttribute(gemm_bf<0>, cudaFuncAttributeMaxDynamicSharedMemorySize, G_SMEM_BYTES);
    cudaFuncSetAttribute(gemm_bf<1>, cudaFuncAttributeMaxDynamicSharedMemorySize, G_SMEM_BYTES);

    // GEMM1: qkvb = bf16(swish(x @ W_fc + b_fc))
    dim3 g1(QKVN / 128, NROWS / 128);
    gemm_bf<0><<<g1, 256, G_SMEM_BYTES>>>(xb, wbT, b_fc, nullptr, qkvb, NROWS, QKVN, DD);

    // V^T for the PV mma
    dim3 gv(LL / 64, NH, BB);
    vtrans_kernel<<<gv, 256>>>(qkvb, vt);

    // FlashAttention-2 (bf16, ldmatrix)
    cudaFuncSetAttribute(attn_fa, cudaFuncAttributeMaxDynamicSharedMemorySize, A_SMEM_BYTES);
    dim3 ga(LL / 64, NH, BB);
    attn_fa<<<ga, 128, A_SMEM_BYTES>>>(qkvb, vt, nvb);

    // GEMM2: hb = x + swish(nv @ W_fc2 + b_fc2)
    dim3 g2(DD / 128, NROWS / 128);
    gemm_bf<1><<<g2, 256, G_SMEM_BYTES>>>(nvb, w2bT, b_fc2, x, hb, NROWS, DD, DD);

    // LayerNorm -> out
    ln_kernel<<<NROWS, 256>>>(hb, out);
}